// round 11
// baseline (speedup 1.0000x reference)
#include <cuda_runtime.h>
#include <cuda_bf16.h>
#include <math.h>
#include <cstdint>

#define BB 4
#define TT 4096
#define DD 1024
#define HH 8
#define DH 128
#define MM (BB*TT)          // 16384 rows
#define NEGV (-1000000.0f)

// ---------------- scratch (static device allocations; no cudaMalloc) ----------------
__device__ __nv_bfloat16 g_xnb[(size_t)MM * DD];        // 32 MB  LayerNorm output (bf16)
__device__ __nv_bfloat16 g_wbT[3][(size_t)DD * DD];     // 6 MB   W transposed to [N][K] bf16
__device__ __nv_bfloat16 g_qb [(size_t)MM * DD];        // 32 MB  q (bf16, bias added)
__device__ __nv_bfloat16 g_ekb[(size_t)MM * DD];        // 32 MB  exp(k) (bf16; 0 on padded rows)
__device__ __nv_bfloat16 g_vb [(size_t)MM * DD];        // 32 MB  masked v (bf16)
__device__ float g_att[BB * HH * DH * DH];              // 2 MB   unnormalized att (atomic accum)
__device__ float g_Z [BB * DD];                         // time-softmax denominators

__device__ __forceinline__ uint32_t smem_u32(const void* p) {
    uint32_t a;
    asm("{ .reg .u64 t; cvta.to.shared.u64 t, %1; cvt.u32.u64 %0, t; }" : "=r"(a) : "l"(p));
    return a;
}
__device__ __forceinline__ void ldsm_x4(uint32_t& r0, uint32_t& r1, uint32_t& r2, uint32_t& r3, uint32_t a) {
    asm volatile("ldmatrix.sync.aligned.m8n8.x4.shared.b16 {%0,%1,%2,%3}, [%4];"
                 : "=r"(r0), "=r"(r1), "=r"(r2), "=r"(r3) : "r"(a));
}
__device__ __forceinline__ void ldsm_x4_t(uint32_t& r0, uint32_t& r1, uint32_t& r2, uint32_t& r3, uint32_t a) {
    asm volatile("ldmatrix.sync.aligned.m8n8.x4.trans.shared.b16 {%0,%1,%2,%3}, [%4];"
                 : "=r"(r0), "=r"(r1), "=r"(r2), "=r"(r3) : "r"(a));
}
__device__ __forceinline__ void mma16816(float* d, uint32_t a0, uint32_t a1, uint32_t a2, uint32_t a3,
                                         uint32_t b0, uint32_t b1) {
    asm volatile("mma.sync.aligned.m16n8k16.row.col.f32.bf16.bf16.f32 "
                 "{%0,%1,%2,%3}, {%4,%5,%6,%7}, {%8,%9}, {%0,%1,%2,%3};"
                 : "+f"(d[0]), "+f"(d[1]), "+f"(d[2]), "+f"(d[3])
                 : "r"(a0), "r"(a1), "r"(a2), "r"(a3), "r"(b0), "r"(b1));
}
#define CP_ASYNC16(sm, gm) asm volatile("cp.async.cg.shared.global [%0], [%1], 16;" :: "r"(sm), "l"(gm))
#define CP_COMMIT()        asm volatile("cp.async.commit_group;" ::: "memory")

// ---------------- LayerNorm -> bf16 xn ----------------
__global__ __launch_bounds__(256) void ln_kernel(const float* __restrict__ x,
                                                 const float* __restrict__ gamma,
                                                 const float* __restrict__ beta) {
    __shared__ float red[18];
    int row = blockIdx.x;
    int tid = threadIdx.x;
    const float4* xr = (const float4*)(x + (size_t)row * DD);
    float4 v = xr[tid];
    float s = v.x + v.y + v.z + v.w;
    #pragma unroll
    for (int o = 16; o; o >>= 1) s += __shfl_xor_sync(0xffffffffu, s, o);
    if ((tid & 31) == 0) red[tid >> 5] = s;
    __syncthreads();
    if (tid < 32) {
        float t = (tid < 8) ? red[tid] : 0.f;
        #pragma unroll
        for (int o = 4; o; o >>= 1) t += __shfl_xor_sync(0xffffffffu, t, o);
        if (tid == 0) red[16] = t;
    }
    __syncthreads();
    float mu = red[16] * (1.0f / DD);
    float d0 = v.x - mu, d1 = v.y - mu, d2 = v.z - mu, d3 = v.w - mu;
    float sq = d0*d0 + d1*d1 + d2*d2 + d3*d3;
    #pragma unroll
    for (int o = 16; o; o >>= 1) sq += __shfl_xor_sync(0xffffffffu, sq, o);
    if ((tid & 31) == 0) red[tid >> 5] = sq;
    __syncthreads();
    if (tid < 32) {
        float t = (tid < 8) ? red[tid] : 0.f;
        #pragma unroll
        for (int o = 4; o; o >>= 1) t += __shfl_xor_sync(0xffffffffu, t, o);
        if (tid == 0) red[17] = t;
    }
    __syncthreads();
    float inv = rsqrtf(red[17] * (1.0f / DD) + 1e-5f);
    float4 g  = ((const float4*)gamma)[tid];
    float4 bt = ((const float4*)beta)[tid];
    float o0 = d0 * inv * g.x + bt.x;
    float o1 = d1 * inv * g.y + bt.y;
    float o2 = d2 * inv * g.z + bt.z;
    float o3 = d3 * inv * g.w + bt.w;
    __nv_bfloat162* xo = (__nv_bfloat162*)(g_xnb + (size_t)row * DD);
    xo[tid * 2]     = __floats2bfloat162_rn(o0, o1);
    xo[tid * 2 + 1] = __floats2bfloat162_rn(o2, o3);
}

// ---------------- W -> bf16 transposed [N][K] ----------------
__global__ void wconv_kernel(const float* __restrict__ Wq,
                             const float* __restrict__ Wk,
                             const float* __restrict__ Wv) {
    __shared__ float t[32][33];
    int z = blockIdx.z;
    const float* W = (z == 0) ? Wq : (z == 1) ? Wk : Wv;
    int k = blockIdx.y * 32 + threadIdx.y;
    int n = blockIdx.x * 32 + threadIdx.x;
    t[threadIdx.y][threadIdx.x] = W[(size_t)k * DD + n];
    __syncthreads();
    int n2 = blockIdx.x * 32 + threadIdx.y;
    int k2 = blockIdx.y * 32 + threadIdx.x;
    g_wbT[z][(size_t)n2 * DD + k2] = __float2bfloat16_rn(t[threadIdx.x][threadIdx.y]);
}

// ================= QKV GEMM: 128x128 CTA tile, 4 warps of 64x64, 2 CTAs/SM =================
// 128 threads/CTA -> 256-reg budget for the 64x64 warp tile; BK=64, 3 stages, 1 sync/chunk.
#define BK 64
#define APAD 72
#define QM 128
#define QN 128
#define STAGES 3
#define ABUF (QM * APAD)                       // elems per A stage
#define BBUF (QN * APAD)
#define QSMEM (STAGES * (ABUF + BBUF) * 2)     // 110592 bytes -> 2 CTAs/SM
#define NCHUNK (DD / BK)                       // 16

__device__ __forceinline__ void qload(uint32_t dA, uint32_t dB,
                                      const __nv_bfloat16* gA, const __nv_bfloat16* gB) {
    const uint32_t rowStepS = 16 * APAD * 2;
    const size_t   rowStepG = (size_t)16 * DD;
    #pragma unroll
    for (int i = 0; i < 8; i++) CP_ASYNC16(dA + i * rowStepS, gA + i * rowStepG);
    #pragma unroll
    for (int i = 0; i < 8; i++) CP_ASYNC16(dB + i * rowStepS, gB + i * rowStepG);
    CP_COMMIT();
}

__global__ __launch_bounds__(128, 2) void qkv_mma_kernel(
    const float* __restrict__ bq, const float* __restrict__ bk,
    const float* __restrict__ bv, const float* __restrict__ mask) {
    extern __shared__ __nv_bfloat16 qsm[];
    __nv_bfloat16* As = qsm;                    // STAGES x ABUF
    __nv_bfloat16* Bs = qsm + STAGES * ABUF;    // STAGES x BBUF
    int tid = threadIdx.x;
    int wid = tid >> 5, lane = tid & 31;
    int mat = blockIdx.z;
    int m0 = blockIdx.y * QM, n0 = blockIdx.x * QN;
    const __nv_bfloat16* Ag = g_xnb + (size_t)m0 * DD;
    const __nv_bfloat16* Bg = g_wbT[mat] + (size_t)n0 * DD;
    __nv_bfloat16* C = (mat == 0) ? g_qb : (mat == 1) ? g_ekb : g_vb;
    const float* bias = (mat == 0) ? bq : (mat == 1) ? bk : bv;

    uint32_t sA = smem_u32(As), sB = smem_u32(Bs);
    // loader: row-base = tid>>3 (0..15), chunk = tid&7 (8 x 16B per 128B row-slice)
    int lrow = tid >> 3, lch = tid & 7;
    uint32_t dA0 = sA + (lrow * APAD + lch * 8) * 2;
    uint32_t dB0 = sB + (lrow * APAD + lch * 8) * 2;
    const __nv_bfloat16* gA0 = Ag + (size_t)lrow * DD + lch * 8;
    const __nv_bfloat16* gB0 = Bg + (size_t)lrow * DD + lch * 8;
    const uint32_t aStageB = ABUF * 2, bStageB = BBUF * 2;

    qload(dA0,           dB0,           gA0,      gB0);
    qload(dA0 + aStageB, dB0 + bStageB, gA0 + BK, gB0 + BK);

    int wr = wid >> 1, wc = wid & 1;            // 2 x 2 warps, each 64x64
    float acc[4][8][4];
    #pragma unroll
    for (int i = 0; i < 4; i++)
        #pragma unroll
        for (int j = 0; j < 8; j++)
            #pragma unroll
            for (int c = 0; c < 4; c++) acc[i][j][c] = 0.f;

    int aRow = (lane & 15);
    int aK   = (lane >> 4) * 8;
    int q2 = lane >> 3;
    int bRow = ((q2 >> 1) * 8) + (lane & 7);
    int bK   = (q2 & 1) * 8;

    for (int c = 0; c < NCHUNK; c++) {
        if (c + 1 < NCHUNK) asm volatile("cp.async.wait_group 1;" ::: "memory");
        else                asm volatile("cp.async.wait_group 0;" ::: "memory");
        __syncthreads();
        if (c + 2 < NCHUNK) {
            int s = (c + 2) % 3;
            qload(dA0 + s * aStageB, dB0 + s * bStageB,
                  gA0 + (size_t)(c + 2) * BK, gB0 + (size_t)(c + 2) * BK);
        }

        uint32_t aBase = sA + (c % 3) * aStageB;
        uint32_t bBase = sB + (c % 3) * bStageB;
        #pragma unroll
        for (int ks = 0; ks < 4; ks++) {
            uint32_t af[4][4];
            #pragma unroll
            for (int mt = 0; mt < 4; mt++) {
                uint32_t ad = aBase + ((wr * 64 + mt * 16 + aRow) * APAD + ks * 16 + aK) * 2;
                ldsm_x4(af[mt][0], af[mt][1], af[mt][2], af[mt][3], ad);
            }
            uint32_t bf[8][2];
            #pragma unroll
            for (int g = 0; g < 4; g++) {
                uint32_t bd = bBase + ((wc * 64 + g * 16 + bRow) * APAD + ks * 16 + bK) * 2;
                uint32_t t0, t1, t2, t3;
                ldsm_x4(t0, t1, t2, t3, bd);
                bf[g * 2][0] = t0;     bf[g * 2][1] = t1;
                bf[g * 2 + 1][0] = t2; bf[g * 2 + 1][1] = t3;
            }
            #pragma unroll
            for (int mt = 0; mt < 4; mt++)
                #pragma unroll
                for (int nt = 0; nt < 8; nt++)
                    mma16816(acc[mt][nt], af[mt][0], af[mt][1], af[mt][2], af[mt][3],
                             bf[nt][0], bf[nt][1]);
        }
    }
    __syncthreads();

    // epilogue: bias + transform + bf16 stores (mask/bias hoisted)
    int colBase = n0 + wc * 64 + (lane & 3) * 2;
    int rowBase = m0 + wr * 64 + (lane >> 2);
    float bb0[8], bb1[8];
    #pragma unroll
    for (int nt = 0; nt < 8; nt++) {
        bb0[nt] = __ldg(bias + colBase + nt * 8);
        bb1[nt] = __ldg(bias + colBase + nt * 8 + 1);
    }
    #pragma unroll
    for (int mt = 0; mt < 4; mt++) {
        int r1 = rowBase + mt * 16;
        int r2 = r1 + 8;
        float mk1 = mask[r1], mk2 = mask[r2];
        float a1 = (1.0f - mk1) * NEGV, a2 = (1.0f - mk2) * NEGV;
        #pragma unroll
        for (int nt = 0; nt < 8; nt++) {
            int col = colBase + nt * 8;
            float v0 = acc[mt][nt][0] + bb0[nt], v1 = acc[mt][nt][1] + bb1[nt];
            float v2 = acc[mt][nt][2] + bb0[nt], v3 = acc[mt][nt][3] + bb1[nt];
            if (mat == 1) {
                v0 = __expf(v0 + a1); v1 = __expf(v1 + a1);
                v2 = __expf(v2 + a2); v3 = __expf(v3 + a2);
            } else if (mat == 2) {
                v0 *= mk1; v1 *= mk1; v2 *= mk2; v3 *= mk2;
            }
            *(__nv_bfloat162*)(C + (size_t)r1 * DD + col) = __floats2bfloat162_rn(v0, v1);
            *(__nv_bfloat162*)(C + (size_t)r2 * DD + col) = __floats2bfloat162_rn(v2, v3);
        }
    }
}

// ---------------- zero att + Z ----------------
__global__ void zero_kernel() {
    int i = blockIdx.x * 256 + threadIdx.x;
    if (i < BB*HH*DH*DH) g_att[i] = 0.f;
    if (i < BB*DD)       g_Z[i]   = 0.f;
}

// ---------------- Z = column sums of ek over time ----------------
__global__ __launch_bounds__(256) void z_kernel() {
    int b = blockIdx.x;
    int d = blockIdx.y * 256 + threadIdx.x;
    int t0 = blockIdx.z * (TT / 8);
    const __nv_bfloat16* p = g_ekb + ((size_t)(b * TT + t0)) * DD + d;
    float s = 0.f;
    #pragma unroll 8
    for (int t = 0; t < TT / 8; t++) s += __bfloat162float(p[(size_t)t * DD]);
    atomicAdd(&g_Z[b * DD + d], s);
}

// ---------------- att = ek^T v via mma (trans ldmatrix both operands) ----------------
#define ATSPLIT 16
#define EPAD 136
__global__ __launch_bounds__(256) void att_mma_kernel() {
    __shared__ __nv_bfloat16 eks[2][32 * EPAD];
    __shared__ __nv_bfloat16 vs [2][32 * EPAD];
    int tid = threadIdx.x;
    int wid = tid >> 5, lane = tid & 31;
    int bh = blockIdx.x;
    int b = bh >> 3, h = bh & 7;
    int tstart = blockIdx.y * (TT / ATSPLIT);
    const __nv_bfloat16* ekg = g_ekb + ((size_t)(b * TT + tstart)) * DD + h * DH;
    const __nv_bfloat16* vg  = g_vb  + ((size_t)(b * TT + tstart)) * DD + h * DH;

    uint32_t sE = smem_u32(eks), sV = smem_u32(vs);
    int lrow0 = tid >> 4, lc0 = (tid & 15);
    int lrow1 = (tid + 256) >> 4, lc1 = (tid & 15);

    #define ALOAD(buf, c) {                                                              \
        size_t roff0 = (size_t)((c) * 32 + lrow0) * DD + lc0 * 8;                        \
        size_t roff1 = (size_t)((c) * 32 + lrow1) * DD + lc1 * 8;                        \
        uint32_t d0 = (buf) * 32 * EPAD * 2 + (lrow0 * EPAD + lc0 * 8) * 2;              \
        uint32_t d1 = (buf) * 32 * EPAD * 2 + (lrow1 * EPAD + lc1 * 8) * 2;              \
        CP_ASYNC16(sE + d0, ekg + roff0);  CP_ASYNC16(sE + d1, ekg + roff1);             \
        CP_ASYNC16(sV + d0, vg  + roff0);  CP_ASYNC16(sV + d1, vg  + roff1);             \
        CP_COMMIT(); }

    ALOAD(0, 0);

    int wr = wid >> 2, wc = wid & 3;
    float acc[4][4][4];
    #pragma unroll
    for (int i = 0; i < 4; i++)
        #pragma unroll
        for (int j = 0; j < 4; j++)
            #pragma unroll
            for (int c = 0; c < 4; c++) acc[i][j][c] = 0.f;

    int rowf = ((lane >> 4) & 1) * 8 + (lane & 7);
    int colf = ((lane >> 3) & 1) * 8;

    int buf = 0;
    const int NC = (TT / ATSPLIT) / 32;
    for (int c = 0; c < NC; c++) {
        if (c + 1 < NC) {
            ALOAD(buf ^ 1, c + 1);
            asm volatile("cp.async.wait_group 1;" ::: "memory");
        } else {
            asm volatile("cp.async.wait_group 0;" ::: "memory");
        }
        __syncthreads();

        uint32_t eBase = sE + buf * 32 * EPAD * 2;
        uint32_t vBase = sV + buf * 32 * EPAD * 2;
        #pragma unroll
        for (int ks = 0; ks < 2; ks++) {
            uint32_t af[4][4];
            #pragma unroll
            for (int mt = 0; mt < 4; mt++) {
                uint32_t ad = eBase + ((ks * 16 + rowf) * EPAD + wr * 64 + mt * 16 + colf) * 2;
                ldsm_x4_t(af[mt][0], af[mt][1], af[mt][2], af[mt][3], ad);
            }
            uint32_t bf[4][2];
            #pragma unroll
            for (int g = 0; g < 2; g++) {
                uint32_t bd = vBase + ((ks * 16 + rowf) * EPAD + wc * 32 + g * 16 + colf) * 2;
                uint32_t t0, t1, t2, t3;
                ldsm_x4_t(t0, t1, t2, t3, bd);
                bf[g * 2][0] = t0;     bf[g * 2][1] = t2;
                bf[g * 2 + 1][0] = t1; bf[g * 2 + 1][1] = t3;
            }
            #pragma unroll
            for (int mt = 0; mt < 4; mt++)
                #pragma unroll
                for (int nt = 0; nt < 4; nt++)
                    mma16816(acc[mt][nt], af[mt][0], af[mt][1], af[mt][2], af[mt][3],
                             bf[nt][0], bf[nt][1]);
        }
        __syncthreads();
        buf ^= 1;
    }

    float* attp = g_att + (size_t)bh * DH * DH;
    int dr = wr * 64 + (lane >> 2);
    int lcb = wc * 32 + (lane & 3) * 2;
    #pragma unroll
    for (int mt = 0; mt < 4; mt++)
        #pragma unroll
        for (int nt = 0; nt < 4; nt++) {
            int d1 = dr + mt * 16, l0 = lcb + nt * 8;
            atomicAdd(&attp[d1 * DH + l0],       acc[mt][nt][0]);
            atomicAdd(&attp[d1 * DH + l0 + 1],   acc[mt][nt][1]);
            atomicAdd(&attp[(d1+8) * DH + l0],   acc[mt][nt][2]);
            atomicAdd(&attp[(d1+8) * DH + l0+1], acc[mt][nt][3]);
        }
}

// ---------------- y = softmax_row(q) @ (att/Z) via mma ; out = x + y ----------------
#define YSMEM (2 * 128 * EPAD * 2)
__global__ __launch_bounds__(256) void y_mma_kernel(const float* __restrict__ x,
                                                    float* __restrict__ out) {
    extern __shared__ __nv_bfloat16 ysm[];
    __nv_bfloat16* att_s = ysm;
    __nv_bfloat16* qs    = ysm + 128 * EPAD;
    int tid = threadIdx.x;
    int wid = tid >> 5, lane = tid & 31;
    int t0 = blockIdx.x * 128;
    int h = blockIdx.y;
    int b = blockIdx.z;
    int bh = b * HH + h;

    {
        int d = tid >> 1;
        int lp = (tid & 1) * 64;
        float zinv = 1.0f / g_Z[b * DD + h * DH + d];
        const float* ap = g_att + (size_t)bh * DH * DH + d * DH + lp;
        __nv_bfloat162* dst = (__nv_bfloat162*)(att_s + d * EPAD + lp);
        #pragma unroll
        for (int c = 0; c < 64; c += 4) {
            float4 av = *(const float4*)(ap + c);
            dst[c/2]   = __floats2bfloat162_rn(av.x * zinv, av.y * zinv);
            dst[c/2+1] = __floats2bfloat162_rn(av.z * zinv, av.w * zinv);
        }
    }
    for (int r = wid; r < 128; r += 8) {
        const __nv_bfloat16* qrow = g_qb + ((size_t)(b * TT + t0 + r)) * DD + h * DH + lane * 4;
        uint2 u = *(const uint2*)qrow;
        __nv_bfloat162 p0 = *(__nv_bfloat162*)&u.x;
        __nv_bfloat162 p1 = *(__nv_bfloat162*)&u.y;
        float q0 = __bfloat162float(p0.x), q1 = __bfloat162float(p0.y);
        float q2 = __bfloat162float(p1.x), q3 = __bfloat162float(p1.y);
        float mx = fmaxf(fmaxf(q0, q1), fmaxf(q2, q3));
        #pragma unroll
        for (int o = 16; o; o >>= 1) mx = fmaxf(mx, __shfl_xor_sync(0xffffffffu, mx, o));
        float e0 = __expf(q0 - mx), e1 = __expf(q1 - mx);
        float e2 = __expf(q2 - mx), e3 = __expf(q3 - mx);
        float s = e0 + e1 + e2 + e3;
        #pragma unroll
        for (int o = 16; o; o >>= 1) s += __shfl_xor_sync(0xffffffffu, s, o);
        float inv = 1.0f / s;
        __nv_bfloat162* dst = (__nv_bfloat162*)(qs + r * EPAD + lane * 4);
        dst[0] = __floats2bfloat162_rn(e0 * inv, e1 * inv);
        dst[1] = __floats2bfloat162_rn(e2 * inv, e3 * inv);
    }
    __syncthreads();

    uint32_t sQ = smem_u32(qs), sAt = smem_u32(att_s);
    int wr = wid >> 2, wc = wid & 3;
    float acc[4][4][4];
    #pragma unroll
    for (int i = 0; i < 4; i++)
        #pragma unroll
        for (int j = 0; j < 4; j++)
            #pragma unroll
            for (int c = 0; c < 4; c++) acc[i][j][c] = 0.f;

    int aRow = (lane & 15);
    int aK   = (lane >> 4) * 8;
    int rowf = ((lane >> 4) & 1) * 8 + (lane & 7);
    int colf = ((lane >> 3) & 1) * 8;

    #pragma unroll
    for (int ks = 0; ks < 8; ks++) {
        uint32_t af[4][4];
        #pragma unroll
        for (int mt = 0; mt < 4; mt++) {
            uint32_t ad = sQ + ((wr * 64 + mt * 16 + aRow) * EPAD + ks * 16 + aK) * 2;
            ldsm_x4(af[mt][0], af[mt][1], af[mt][2], af[mt][3], ad);
        }
        uint32_t bf[4][2];
        #pragma unroll
        for (int g = 0; g < 2; g++) {
            uint32_t bd = sAt + ((ks * 16 + rowf) * EPAD + wc * 32 + g * 16 + colf) * 2;
            uint32_t u0, u1, u2, u3;
            ldsm_x4_t(u0, u1, u2, u3, bd);
            bf[g * 2][0] = u0;     bf[g * 2][1] = u2;
            bf[g * 2 + 1][0] = u1; bf[g * 2 + 1][1] = u3;
        }
        #pragma unroll
        for (int mt = 0; mt < 4; mt++)
            #pragma unroll
            for (int nt = 0; nt < 4; nt++)
                mma16816(acc[mt][nt], af[mt][0], af[mt][1], af[mt][2], af[mt][3],
                         bf[nt][0], bf[nt][1]);
    }

    int rb = wr * 64 + (lane >> 2);
    int cb = h * DH + wc * 32 + (lane & 3) * 2;
    #pragma unroll
    for (int mt = 0; mt < 4; mt++) {
        int r1 = t0 + rb + mt * 16;
        int r2 = r1 + 8;
        #pragma unroll
        for (int nt = 0; nt < 4; nt++) {
            size_t base1 = (size_t)(b * TT + r1) * DD + cb + nt * 8;
            size_t base2 = (size_t)(b * TT + r2) * DD + cb + nt * 8;
            float2 x1 = *(const float2*)(x + base1);
            float2 x2 = *(const float2*)(x + base2);
            float2 o1 = { x1.x + acc[mt][nt][0], x1.y + acc[mt][nt][1] };
            float2 o2 = { x2.x + acc[mt][nt][2], x2.y + acc[mt][nt][3] };
            *(float2*)(out + base1) = o1;
            *(float2*)(out + base2) = o2;
        }
    }
}

// ---------------- launch ----------------
extern "C" void kernel_launch(void* const* d_in, const int* in_sizes, int n_in,
                              void* d_out, int out_size) {
    const float* x        = (const float*)d_in[0];
    const float* src_mask = (const float*)d_in[1];
    const float* Wq       = (const float*)d_in[2];
    const float* bq       = (const float*)d_in[3];
    const float* Wk       = (const float*)d_in[4];
    const float* bk       = (const float*)d_in[5];
    const float* Wv       = (const float*)d_in[6];
    const float* bv       = (const float*)d_in[7];
    const float* gamma    = (const float*)d_in[8];
    const float* beta     = (const float*)d_in[9];
    float* out = (float*)d_out;

    cudaFuncSetAttribute(qkv_mma_kernel, cudaFuncAttributeMaxDynamicSharedMemorySize, QSMEM);
    cudaFuncSetAttribute(y_mma_kernel,  cudaFuncAttributeMaxDynamicSharedMemorySize, YSMEM);

    // order chosen so qkv_mma_kernel is launch index 3 (the one ncu profiles)
    ln_kernel<<<MM, 256>>>(x, gamma, beta);
    wconv_kernel<<<dim3(32, 32, 3), dim3(32, 32)>>>(Wq, Wk, Wv);
    zero_kernel<<<(BB*HH*DH*DH + 255) / 256, 256>>>();
    qkv_mma_kernel<<<dim3(DD / QN, MM / QM, 3), 128, QSMEM>>>(bq, bk, bv, src_mask);
    z_kernel<<<dim3(BB, DD / 256, 8), 256>>>();
    att_mma_kernel<<<dim3(BB*HH, ATSPLIT), 256>>>();
    y_mma_kernel<<<dim3(TT/128, HH, BB), 256, YSMEM>>>(x, out);
}

// round 14
// speedup vs baseline: 1.0989x; 1.0989x over previous
#include <cuda_runtime.h>
#include <cuda_bf16.h>
#include <math.h>
#include <cstdint>

#define BB 4
#define TT 4096
#define DD 1024
#define HH 8
#define DH 128
#define MM (BB*TT)          // 16384 rows
#define NEGV (-1000000.0f)

// ---------------- scratch (static device allocations; no cudaMalloc) ----------------
__device__ __nv_bfloat16 g_xnb[(size_t)MM * DD];        // 32 MB  LayerNorm output (bf16)
__device__ __nv_bfloat16 g_wbT[3][(size_t)DD * DD];     // 6 MB   W transposed to [N][K] bf16
__device__ __nv_bfloat16 g_qb [(size_t)MM * DD];        // 32 MB  q (bf16, bias added)
__device__ __nv_bfloat16 g_ekb[(size_t)MM * DD];        // 32 MB  exp(k) (bf16; 0 on padded rows)
__device__ __nv_bfloat16 g_vb [(size_t)MM * DD];        // 32 MB  masked v (bf16)
__device__ float g_att[BB * HH * DH * DH];              // 2 MB   unnormalized att (atomic accum)
__device__ float g_Z [BB * DD];                         // time-softmax denominators

__device__ __forceinline__ uint32_t smem_u32(const void* p) {
    uint32_t a;
    asm("{ .reg .u64 t; cvta.to.shared.u64 t, %1; cvt.u32.u64 %0, t; }" : "=r"(a) : "l"(p));
    return a;
}
__device__ __forceinline__ void ldsm_x4(uint32_t& r0, uint32_t& r1, uint32_t& r2, uint32_t& r3, uint32_t a) {
    asm volatile("ldmatrix.sync.aligned.m8n8.x4.shared.b16 {%0,%1,%2,%3}, [%4];"
                 : "=r"(r0), "=r"(r1), "=r"(r2), "=r"(r3) : "r"(a));
}
__device__ __forceinline__ void ldsm_x4_t(uint32_t& r0, uint32_t& r1, uint32_t& r2, uint32_t& r3, uint32_t a) {
    asm volatile("ldmatrix.sync.aligned.m8n8.x4.trans.shared.b16 {%0,%1,%2,%3}, [%4];"
                 : "=r"(r0), "=r"(r1), "=r"(r2), "=r"(r3) : "r"(a));
}
__device__ __forceinline__ void mma16816(float* d, uint32_t a0, uint32_t a1, uint32_t a2, uint32_t a3,
                                         uint32_t b0, uint32_t b1) {
    asm volatile("mma.sync.aligned.m16n8k16.row.col.f32.bf16.bf16.f32 "
                 "{%0,%1,%2,%3}, {%4,%5,%6,%7}, {%8,%9}, {%0,%1,%2,%3};"
                 : "+f"(d[0]), "+f"(d[1]), "+f"(d[2]), "+f"(d[3])
                 : "r"(a0), "r"(a1), "r"(a2), "r"(a3), "r"(b0), "r"(b1));
}
#define CP_ASYNC16(sm, gm) asm volatile("cp.async.cg.shared.global [%0], [%1], 16;" :: "r"(sm), "l"(gm))
#define CP_COMMIT()        asm volatile("cp.async.commit_group;" ::: "memory")

// ---------------- LayerNorm -> bf16 xn ----------------
__global__ __launch_bounds__(256) void ln_kernel(const float* __restrict__ x,
                                                 const float* __restrict__ gamma,
                                                 const float* __restrict__ beta) {
    __shared__ float red[18];
    int row = blockIdx.x;
    int tid = threadIdx.x;
    const float4* xr = (const float4*)(x + (size_t)row * DD);
    float4 v = xr[tid];
    float s = v.x + v.y + v.z + v.w;
    #pragma unroll
    for (int o = 16; o; o >>= 1) s += __shfl_xor_sync(0xffffffffu, s, o);
    if ((tid & 31) == 0) red[tid >> 5] = s;
    __syncthreads();
    if (tid < 32) {
        float t = (tid < 8) ? red[tid] : 0.f;
        #pragma unroll
        for (int o = 4; o; o >>= 1) t += __shfl_xor_sync(0xffffffffu, t, o);
        if (tid == 0) red[16] = t;
    }
    __syncthreads();
    float mu = red[16] * (1.0f / DD);
    float d0 = v.x - mu, d1 = v.y - mu, d2 = v.z - mu, d3 = v.w - mu;
    float sq = d0*d0 + d1*d1 + d2*d2 + d3*d3;
    #pragma unroll
    for (int o = 16; o; o >>= 1) sq += __shfl_xor_sync(0xffffffffu, sq, o);
    if ((tid & 31) == 0) red[tid >> 5] = sq;
    __syncthreads();
    if (tid < 32) {
        float t = (tid < 8) ? red[tid] : 0.f;
        #pragma unroll
        for (int o = 4; o; o >>= 1) t += __shfl_xor_sync(0xffffffffu, t, o);
        if (tid == 0) red[17] = t;
    }
    __syncthreads();
    float inv = rsqrtf(red[17] * (1.0f / DD) + 1e-5f);
    float4 g  = ((const float4*)gamma)[tid];
    float4 bt = ((const float4*)beta)[tid];
    float o0 = d0 * inv * g.x + bt.x;
    float o1 = d1 * inv * g.y + bt.y;
    float o2 = d2 * inv * g.z + bt.z;
    float o3 = d3 * inv * g.w + bt.w;
    __nv_bfloat162* xo = (__nv_bfloat162*)(g_xnb + (size_t)row * DD);
    xo[tid * 2]     = __floats2bfloat162_rn(o0, o1);
    xo[tid * 2 + 1] = __floats2bfloat162_rn(o2, o3);
}

// ---------------- W -> bf16 transposed [N][K], fused zero of g_att / g_Z ----------------
__global__ void wconv_kernel(const float* __restrict__ Wq,
                             const float* __restrict__ Wk,
                             const float* __restrict__ Wv) {
    __shared__ float t[32][33];
    int z = blockIdx.z;
    const float* W = (z == 0) ? Wq : (z == 1) ? Wk : Wv;
    int k = blockIdx.y * 32 + threadIdx.y;
    int n = blockIdx.x * 32 + threadIdx.x;
    t[threadIdx.y][threadIdx.x] = W[(size_t)k * DD + n];

    // fused zeroing (no sync dependence on the transpose)
    int bid = (z * 32 + blockIdx.y) * 32 + blockIdx.x;
    int gidx = bid * 1024 + threadIdx.y * 32 + threadIdx.x;
    if (gidx < BB*HH*DH*DH) g_att[gidx] = 0.f;
    if (gidx < BB*DD)       g_Z[gidx]   = 0.f;

    __syncthreads();
    int n2 = blockIdx.x * 32 + threadIdx.y;
    int k2 = blockIdx.y * 32 + threadIdx.x;
    g_wbT[z][(size_t)n2 * DD + k2] = __float2bfloat16_rn(t[threadIdx.x][threadIdx.y]);
}

// ================= QKV GEMM: 128x128 CTA tile, 8 warps of 64x32, 2 CTAs/SM =================
// (R10 configuration — best measured: 288us, tensor 58.8%)
#define BK 64
#define APAD 72
#define QM 128
#define QN 128
#define STAGES 3
#define ABUF (QM * APAD)
#define BBUF (QN * APAD)
#define QSMEM (STAGES * (ABUF + BBUF) * 2)     // 110592 bytes -> 2 CTAs/SM
#define NCHUNK (DD / BK)                       // 16

__device__ __forceinline__ void qload(uint32_t dA, uint32_t dB,
                                      const __nv_bfloat16* gA, const __nv_bfloat16* gB) {
    const uint32_t rowStepS = 32 * APAD * 2;
    const size_t   rowStepG = (size_t)32 * DD;
    #pragma unroll
    for (int i = 0; i < 4; i++) CP_ASYNC16(dA + i * rowStepS, gA + i * rowStepG);
    #pragma unroll
    for (int i = 0; i < 4; i++) CP_ASYNC16(dB + i * rowStepS, gB + i * rowStepG);
    CP_COMMIT();
}

__global__ __launch_bounds__(256, 2) void qkv_mma_kernel(
    const float* __restrict__ bq, const float* __restrict__ bk,
    const float* __restrict__ bv, const float* __restrict__ mask) {
    extern __shared__ __nv_bfloat16 qsm[];
    __nv_bfloat16* As = qsm;
    __nv_bfloat16* Bs = qsm + STAGES * ABUF;
    int tid = threadIdx.x;
    int wid = tid >> 5, lane = tid & 31;
    int mat = blockIdx.z;
    int m0 = blockIdx.y * QM, n0 = blockIdx.x * QN;
    const __nv_bfloat16* Ag = g_xnb + (size_t)m0 * DD;
    const __nv_bfloat16* Bg = g_wbT[mat] + (size_t)n0 * DD;
    __nv_bfloat16* C = (mat == 0) ? g_qb : (mat == 1) ? g_ekb : g_vb;
    const float* bias = (mat == 0) ? bq : (mat == 1) ? bk : bv;

    uint32_t sA = smem_u32(As), sB = smem_u32(Bs);
    int lrow = tid >> 3, lch = tid & 7;
    uint32_t dA0 = sA + (lrow * APAD + lch * 8) * 2;
    uint32_t dB0 = sB + (lrow * APAD + lch * 8) * 2;
    const __nv_bfloat16* gA0 = Ag + (size_t)lrow * DD + lch * 8;
    const __nv_bfloat16* gB0 = Bg + (size_t)lrow * DD + lch * 8;
    const uint32_t aStageB = ABUF * 2, bStageB = BBUF * 2;

    qload(dA0,           dB0,           gA0,      gB0);
    qload(dA0 + aStageB, dB0 + bStageB, gA0 + BK, gB0 + BK);

    int wr = wid >> 2, wc = wid & 3;            // 2 x 4 warps, each 64x32
    float acc[4][4][4];
    #pragma unroll
    for (int i = 0; i < 4; i++)
        #pragma unroll
        for (int j = 0; j < 4; j++)
            #pragma unroll
            for (int c = 0; c < 4; c++) acc[i][j][c] = 0.f;

    int aRow = (lane & 15);
    int aK   = (lane >> 4) * 8;
    int q2 = lane >> 3;
    int bRow = ((q2 >> 1) * 8) + (lane & 7);
    int bK   = (q2 & 1) * 8;

    for (int c = 0; c < NCHUNK; c++) {
        if (c + 1 < NCHUNK) asm volatile("cp.async.wait_group 1;" ::: "memory");
        else                asm volatile("cp.async.wait_group 0;" ::: "memory");
        __syncthreads();
        if (c + 2 < NCHUNK) {
            int s = (c + 2) % 3;
            qload(dA0 + s * aStageB, dB0 + s * bStageB,
                  gA0 + (size_t)(c + 2) * BK, gB0 + (size_t)(c + 2) * BK);
        }

        uint32_t aBase = sA + (c % 3) * aStageB;
        uint32_t bBase = sB + (c % 3) * bStageB;
        #pragma unroll
        for (int ks = 0; ks < 4; ks++) {
            uint32_t af[4][4];
            #pragma unroll
            for (int mt = 0; mt < 4; mt++) {
                uint32_t ad = aBase + ((wr * 64 + mt * 16 + aRow) * APAD + ks * 16 + aK) * 2;
                ldsm_x4(af[mt][0], af[mt][1], af[mt][2], af[mt][3], ad);
            }
            uint32_t bf[4][2];
            #pragma unroll
            for (int g = 0; g < 2; g++) {
                uint32_t bd = bBase + ((wc * 32 + g * 16 + bRow) * APAD + ks * 16 + bK) * 2;
                uint32_t t0, t1, t2, t3;
                ldsm_x4(t0, t1, t2, t3, bd);
                bf[g * 2][0] = t0;     bf[g * 2][1] = t1;
                bf[g * 2 + 1][0] = t2; bf[g * 2 + 1][1] = t3;
            }
            #pragma unroll
            for (int mt = 0; mt < 4; mt++)
                #pragma unroll
                for (int nt = 0; nt < 4; nt++)
                    mma16816(acc[mt][nt], af[mt][0], af[mt][1], af[mt][2], af[mt][3],
                             bf[nt][0], bf[nt][1]);
        }
    }
    __syncthreads();

    // epilogue: bias + transform + bf16 stores (mask/bias hoisted)
    int colBase = n0 + wc * 32 + (lane & 3) * 2;
    int rowBase = m0 + wr * 64 + (lane >> 2);
    float bb0[4], bb1[4];
    #pragma unroll
    for (int nt = 0; nt < 4; nt++) {
        bb0[nt] = __ldg(bias + colBase + nt * 8);
        bb1[nt] = __ldg(bias + colBase + nt * 8 + 1);
    }
    #pragma unroll
    for (int mt = 0; mt < 4; mt++) {
        int r1 = rowBase + mt * 16;
        int r2 = r1 + 8;
        float mk1 = mask[r1], mk2 = mask[r2];
        float a1 = (1.0f - mk1) * NEGV, a2 = (1.0f - mk2) * NEGV;
        #pragma unroll
        for (int nt = 0; nt < 4; nt++) {
            int col = colBase + nt * 8;
            float v0 = acc[mt][nt][0] + bb0[nt], v1 = acc[mt][nt][1] + bb1[nt];
            float v2 = acc[mt][nt][2] + bb0[nt], v3 = acc[mt][nt][3] + bb1[nt];
            if (mat == 1) {
                v0 = __expf(v0 + a1); v1 = __expf(v1 + a1);
                v2 = __expf(v2 + a2); v3 = __expf(v3 + a2);
            } else if (mat == 2) {
                v0 *= mk1; v1 *= mk1; v2 *= mk2; v3 *= mk2;
            }
            *(__nv_bfloat162*)(C + (size_t)r1 * DD + col) = __floats2bfloat162_rn(v0, v1);
            *(__nv_bfloat162*)(C + (size_t)r2 * DD + col) = __floats2bfloat162_rn(v2, v3);
        }
    }
}

// ---------------- att = ek^T v via mma (trans ldmatrix both operands), fused Z ----------------
#define ATSPLIT 16
#define EPAD 136
__global__ __launch_bounds__(256) void att_mma_kernel() {
    __shared__ __nv_bfloat16 eks[2][32 * EPAD];
    __shared__ __nv_bfloat16 vs [2][32 * EPAD];
    int tid = threadIdx.x;
    int wid = tid >> 5, lane = tid & 31;
    int bh = blockIdx.x;
    int b = bh >> 3, h = bh & 7;
    int tstart = blockIdx.y * (TT / ATSPLIT);
    const __nv_bfloat16* ekg = g_ekb + ((size_t)(b * TT + tstart)) * DD + h * DH;
    const __nv_bfloat16* vg  = g_vb  + ((size_t)(b * TT + tstart)) * DD + h * DH;

    uint32_t sE = smem_u32(eks), sV = smem_u32(vs);
    int lrow0 = tid >> 4, lc0 = (tid & 15);
    int lrow1 = (tid + 256) >> 4, lc1 = (tid & 15);

    #define ALOAD(buf, c) {                                                              \
        size_t roff0 = (size_t)((c) * 32 + lrow0) * DD + lc0 * 8;                        \
        size_t roff1 = (size_t)((c) * 32 + lrow1) * DD + lc1 * 8;                        \
        uint32_t d0 = (buf) * 32 * EPAD * 2 + (lrow0 * EPAD + lc0 * 8) * 2;              \
        uint32_t d1 = (buf) * 32 * EPAD * 2 + (lrow1 * EPAD + lc1 * 8) * 2;              \
        CP_ASYNC16(sE + d0, ekg + roff0);  CP_ASYNC16(sE + d1, ekg + roff1);             \
        CP_ASYNC16(sV + d0, vg  + roff0);  CP_ASYNC16(sV + d1, vg  + roff1);             \
        CP_COMMIT(); }

    ALOAD(0, 0);

    int wr = wid >> 2, wc = wid & 3;
    float acc[4][4][4];
    #pragma unroll
    for (int i = 0; i < 4; i++)
        #pragma unroll
        for (int j = 0; j < 4; j++)
            #pragma unroll
            for (int c = 0; c < 4; c++) acc[i][j][c] = 0.f;

    float2 zac = {0.f, 0.f};   // fused Z: threads tid<64 own columns 2*tid, 2*tid+1 (covers 0..127)

    int rowf = ((lane >> 4) & 1) * 8 + (lane & 7);
    int colf = ((lane >> 3) & 1) * 8;

    int buf = 0;
    const int NC = (TT / ATSPLIT) / 32;
    for (int c = 0; c < NC; c++) {
        if (c + 1 < NC) {
            ALOAD(buf ^ 1, c + 1);
            asm volatile("cp.async.wait_group 1;" ::: "memory");
        } else {
            asm volatile("cp.async.wait_group 0;" ::: "memory");
        }
        __syncthreads();

        // fused Z: column sums of exp(k) tile; 64 threads x bf162 = exactly DH=128 cols
        if (tid < 64) {
            #pragma unroll
            for (int r = 0; r < 32; r++) {
                __nv_bfloat162 e = *(__nv_bfloat162*)(&eks[buf][r * EPAD + tid * 2]);
                zac.x += __bfloat162float(e.x);
                zac.y += __bfloat162float(e.y);
            }
        }

        uint32_t eBase = sE + buf * 32 * EPAD * 2;
        uint32_t vBase = sV + buf * 32 * EPAD * 2;
        #pragma unroll
        for (int ks = 0; ks < 2; ks++) {
            uint32_t af[4][4];
            #pragma unroll
            for (int mt = 0; mt < 4; mt++) {
                uint32_t ad = eBase + ((ks * 16 + rowf) * EPAD + wr * 64 + mt * 16 + colf) * 2;
                ldsm_x4_t(af[mt][0], af[mt][1], af[mt][2], af[mt][3], ad);
            }
            uint32_t bf[4][2];
            #pragma unroll
            for (int g = 0; g < 2; g++) {
                uint32_t bd = vBase + ((ks * 16 + rowf) * EPAD + wc * 32 + g * 16 + colf) * 2;
                uint32_t t0, t1, t2, t3;
                ldsm_x4_t(t0, t1, t2, t3, bd);
                bf[g * 2][0] = t0;     bf[g * 2][1] = t2;
                bf[g * 2 + 1][0] = t1; bf[g * 2 + 1][1] = t3;
            }
            #pragma unroll
            for (int mt = 0; mt < 4; mt++)
                #pragma unroll
                for (int nt = 0; nt < 4; nt++)
                    mma16816(acc[mt][nt], af[mt][0], af[mt][1], af[mt][2], af[mt][3],
                             bf[nt][0], bf[nt][1]);
        }
        __syncthreads();
        buf ^= 1;
    }

    if (tid < 64) {
        atomicAdd(&g_Z[b * DD + h * DH + tid * 2],     zac.x);
        atomicAdd(&g_Z[b * DD + h * DH + tid * 2 + 1], zac.y);
    }

    float* attp = g_att + (size_t)bh * DH * DH;
    int dr = wr * 64 + (lane >> 2);
    int lcb = wc * 32 + (lane & 3) * 2;
    #pragma unroll
    for (int mt = 0; mt < 4; mt++)
        #pragma unroll
        for (int nt = 0; nt < 4; nt++) {
            int d1 = dr + mt * 16, l0 = lcb + nt * 8;
            atomicAdd(&attp[d1 * DH + l0],       acc[mt][nt][0]);
            atomicAdd(&attp[d1 * DH + l0 + 1],   acc[mt][nt][1]);
            atomicAdd(&attp[(d1+8) * DH + l0],   acc[mt][nt][2]);
            atomicAdd(&attp[(d1+8) * DH + l0+1], acc[mt][nt][3]);
        }
}

// ---------------- y = softmax_row(q) @ (att/Z) via mma ; out = x + y ----------------
#define YSMEM (2 * 128 * EPAD * 2)
__global__ __launch_bounds__(256) void y_mma_kernel(const float* __restrict__ x,
                                                    float* __restrict__ out) {
    extern __shared__ __nv_bfloat16 ysm[];
    __nv_bfloat16* att_s = ysm;
    __nv_bfloat16* qs    = ysm + 128 * EPAD;
    int tid = threadIdx.x;
    int wid = tid >> 5, lane = tid & 31;
    int t0 = blockIdx.x * 128;
    int h = blockIdx.y;
    int b = blockIdx.z;
    int bh = b * HH + h;

    {
        int d = tid >> 1;
        int lp = (tid & 1) * 64;
        float zinv = 1.0f / g_Z[b * DD + h * DH + d];
        const float* ap = g_att + (size_t)bh * DH * DH + d * DH + lp;
        __nv_bfloat162* dst = (__nv_bfloat162*)(att_s + d * EPAD + lp);
        #pragma unroll
        for (int c = 0; c < 64; c += 4) {
            float4 av = *(const float4*)(ap + c);
            dst[c/2]   = __floats2bfloat162_rn(av.x * zinv, av.y * zinv);
            dst[c/2+1] = __floats2bfloat162_rn(av.z * zinv, av.w * zinv);
        }
    }
    for (int r = wid; r < 128; r += 8) {
        const __nv_bfloat16* qrow = g_qb + ((size_t)(b * TT + t0 + r)) * DD + h * DH + lane * 4;
        uint2 u = *(const uint2*)qrow;
        __nv_bfloat162 p0 = *(__nv_bfloat162*)&u.x;
        __nv_bfloat162 p1 = *(__nv_bfloat162*)&u.y;
        float q0 = __bfloat162float(p0.x), q1 = __bfloat162float(p0.y);
        float q2 = __bfloat162float(p1.x), q3 = __bfloat162float(p1.y);
        float mx = fmaxf(fmaxf(q0, q1), fmaxf(q2, q3));
        #pragma unroll
        for (int o = 16; o; o >>= 1) mx = fmaxf(mx, __shfl_xor_sync(0xffffffffu, mx, o));
        float e0 = __expf(q0 - mx), e1 = __expf(q1 - mx);
        float e2 = __expf(q2 - mx), e3 = __expf(q3 - mx);
        float s = e0 + e1 + e2 + e3;
        #pragma unroll
        for (int o = 16; o; o >>= 1) s += __shfl_xor_sync(0xffffffffu, s, o);
        float inv = 1.0f / s;
        __nv_bfloat162* dst = (__nv_bfloat162*)(qs + r * EPAD + lane * 4);
        dst[0] = __floats2bfloat162_rn(e0 * inv, e1 * inv);
        dst[1] = __floats2bfloat162_rn(e2 * inv, e3 * inv);
    }
    __syncthreads();

    uint32_t sQ = smem_u32(qs), sAt = smem_u32(att_s);
    int wr = wid >> 2, wc = wid & 3;
    float acc[4][4][4];
    #pragma unroll
    for (int i = 0; i < 4; i++)
        #pragma unroll
        for (int j = 0; j < 4; j++)
            #pragma unroll
            for (int c = 0; c < 4; c++) acc[i][j][c] = 0.f;

    int aRow = (lane & 15);
    int aK   = (lane >> 4) * 8;
    int rowf = ((lane >> 4) & 1) * 8 + (lane & 7);
    int colf = ((lane >> 3) & 1) * 8;

    #pragma unroll
    for (int ks = 0; ks < 8; ks++) {
        uint32_t af[4][4];
        #pragma unroll
        for (int mt = 0; mt < 4; mt++) {
            uint32_t ad = sQ + ((wr * 64 + mt * 16 + aRow) * EPAD + ks * 16 + aK) * 2;
            ldsm_x4(af[mt][0], af[mt][1], af[mt][2], af[mt][3], ad);
        }
        uint32_t bf[4][2];
        #pragma unroll
        for (int g = 0; g < 2; g++) {
            uint32_t bd = sAt + ((ks * 16 + rowf) * EPAD + wc * 32 + g * 16 + colf) * 2;
            uint32_t u0, u1, u2, u3;
            ldsm_x4_t(u0, u1, u2, u3, bd);
            bf[g * 2][0] = u0;     bf[g * 2][1] = u2;
            bf[g * 2 + 1][0] = u1; bf[g * 2 + 1][1] = u3;
        }
        #pragma unroll
        for (int mt = 0; mt < 4; mt++)
            #pragma unroll
            for (int nt = 0; nt < 4; nt++)
                mma16816(acc[mt][nt], af[mt][0], af[mt][1], af[mt][2], af[mt][3],
                         bf[nt][0], bf[nt][1]);
    }

    int rb = wr * 64 + (lane >> 2);
    int cb = h * DH + wc * 32 + (lane & 3) * 2;
    #pragma unroll
    for (int mt = 0; mt < 4; mt++) {
        int r1 = t0 + rb + mt * 16;
        int r2 = r1 + 8;
        #pragma unroll
        for (int nt = 0; nt < 4; nt++) {
            size_t base1 = (size_t)(b * TT + r1) * DD + cb + nt * 8;
            size_t base2 = (size_t)(b * TT + r2) * DD + cb + nt * 8;
            float2 x1 = *(const float2*)(x + base1);
            float2 x2 = *(const float2*)(x + base2);
            float2 o1 = { x1.x + acc[mt][nt][0], x1.y + acc[mt][nt][1] };
            float2 o2 = { x2.x + acc[mt][nt][2], x2.y + acc[mt][nt][3] };
            *(float2*)(out + base1) = o1;
            *(float2*)(out + base2) = o2;
        }
    }
}

// ---------------- launch ----------------
extern "C" void kernel_launch(void* const* d_in, const int* in_sizes, int n_in,
                              void* d_out, int out_size) {
    const float* x        = (const float*)d_in[0];
    const float* src_mask = (const float*)d_in[1];
    const float* Wq       = (const float*)d_in[2];
    const float* bq       = (const float*)d_in[3];
    const float* Wk       = (const float*)d_in[4];
    const float* bk       = (const float*)d_in[5];
    const float* Wv       = (const float*)d_in[6];
    const float* bv       = (const float*)d_in[7];
    const float* gamma    = (const float*)d_in[8];
    const float* beta     = (const float*)d_in[9];
    float* out = (float*)d_out;

    cudaFuncSetAttribute(qkv_mma_kernel, cudaFuncAttributeMaxDynamicSharedMemorySize, QSMEM);
    cudaFuncSetAttribute(y_mma_kernel,  cudaFuncAttributeMaxDynamicSharedMemorySize, YSMEM);

    // 5 launches; att_mma_kernel sits at index 3 (the ncu capture slot)
    ln_kernel<<<MM, 256>>>(x, gamma, beta);
    wconv_kernel<<<dim3(32, 32, 3), dim3(32, 32)>>>(Wq, Wk, Wv);
    qkv_mma_kernel<<<dim3(DD / QN, MM / QM, 3), 256, QSMEM>>>(bq, bk, bv, src_mask);
    att_mma_kernel<<<dim3(BB*HH, ATSPLIT), 256>>>();
    y_mma_kernel<<<dim3(TT/128, HH, BB), 256, YSMEM>>>(x, out);
}